// round 2
// baseline (speedup 1.0000x reference)
#include <cuda_runtime.h>

#define H_IMG 512
#define W_IMG 512
#define NPLANES 96            // 32 * 3
#define TW 32
#define TH 64
#define IH 74                 // TH + 10 intermediate rows
#define MS 33                 // intermediate smem row stride (conflict-free)
#define NT 256
#define NBX 16
#define NBY 8
#define NBLK (NBX * NBY * NPLANES)   // 12288
#define C1F 6.5025f
#define C2F 58.5225f
#define NPIX 25165824.0       // 32*3*512*512

__device__ float g_partials[NBLK];
__device__ unsigned int g_count = 0;

#define W11_INIT {0.00102838f, 0.00759871f, 0.03600077f, 0.10936070f, \
                  0.21300560f, 0.26601180f, 0.21300560f, 0.10936070f, \
                  0.03600077f, 0.00759871f, 0.00102838f}

__global__ void __launch_bounds__(NT, 2) ssim_main(const float* __restrict__ gen,
                                                   const float* __restrict__ ref,
                                                   float* __restrict__ out) {
    __shared__ float m1[IH * MS];
    __shared__ float m2[IH * MS];
    __shared__ float mgg[IH * MS];
    __shared__ float mrr[IH * MS];
    __shared__ float mgr[IH * MS];
    __shared__ float wsum[8];
    __shared__ double dsum[8];
    __shared__ bool is_last;

    const float W11[11] = W11_INIT;

    const int tid = threadIdx.x;
    const int x0 = blockIdx.x * TW;
    const int y0 = blockIdx.y * TH;
    const size_t pb = (size_t)blockIdx.z * (size_t)(H_IMG * W_IMG);
    const float* gp = gen + pb;
    const float* rp = ref + pb;

    // ---- Stage A: fused global load (+scale, zero-pad) + horizontal conv ----
    // items: 74 rows x 4 chunks of 8 cols = 296
    for (int item = tid; item < IH * 4; item += NT) {
        int r = item >> 2;
        int c0 = (item & 3) << 3;
        int gy = y0 + r - 5;
        int xbase = x0 + c0 - 5;
        bool rowok = (unsigned)gy < (unsigned)H_IMG;
        const float* grow = gp + (long)gy * W_IMG;
        const float* rrow = rp + (long)gy * W_IMG;

        float a[18], b[18];
#pragma unroll
        for (int t = 0; t < 18; t++) {
            int gx = xbase + t;
            bool ok = rowok && ((unsigned)gx < (unsigned)W_IMG);
            float gv = ok ? grow[gx] : -1.0f;
            float rv = ok ? rrow[gx] : -1.0f;
            a[t] = fmaf(gv, 0.5f, 0.5f);   // pad -> 0 in scaled space
            b[t] = fmaf(rv, 0.5f, 0.5f);
        }

        const int o = r * MS + c0;

        // first-moment fields
        {
            float s1[8], s2[8];
#pragma unroll
            for (int j = 0; j < 8; j++) { s1[j] = 0.f; s2[j] = 0.f; }
#pragma unroll
            for (int k = 0; k < 11; k++) {
                float wk = W11[k];
#pragma unroll
                for (int j = 0; j < 8; j++) {
                    s1[j] = fmaf(wk, a[k + j], s1[j]);
                    s2[j] = fmaf(wk, b[k + j], s2[j]);
                }
            }
#pragma unroll
            for (int j = 0; j < 8; j++) { m1[o + j] = s1[j]; m2[o + j] = s2[j]; }
        }

        // second-moment fields (reuse a,b in place)
        {
            float ab[18];
#pragma unroll
            for (int t = 0; t < 18; t++) ab[t] = a[t] * b[t];
#pragma unroll
            for (int t = 0; t < 18; t++) { a[t] = a[t] * a[t]; b[t] = b[t] * b[t]; }

            float sgg[8], srr[8], sgr[8];
#pragma unroll
            for (int j = 0; j < 8; j++) { sgg[j] = 0.f; srr[j] = 0.f; sgr[j] = 0.f; }
#pragma unroll
            for (int k = 0; k < 11; k++) {
                float wk = W11[k];
#pragma unroll
                for (int j = 0; j < 8; j++) {
                    sgg[j] = fmaf(wk, a[k + j], sgg[j]);
                    srr[j] = fmaf(wk, b[k + j], srr[j]);
                    sgr[j] = fmaf(wk, ab[k + j], sgr[j]);
                }
            }
#pragma unroll
            for (int j = 0; j < 8; j++) {
                mgg[o + j] = sgg[j];
                mrr[o + j] = srr[j];
                mgr[o + j] = sgr[j];
            }
        }
    }
    __syncthreads();

    // ---- Stage B: vertical conv (8 output rows per thread) + SSIM ----
    float lsum = 0.f;
    {
        const int c = tid & 31;
        const int r0 = (tid >> 5) << 3;   // 8 groups * 8 rows = 64

        float o1[8], o2[8], ogg[8], orr[8], ogr[8];

#define VCONV(MARR, OUT)                                                  \
        {                                                                 \
            float v[18];                                                  \
            _Pragma("unroll")                                             \
            for (int t = 0; t < 18; t++) v[t] = MARR[(r0 + t) * MS + c];  \
            _Pragma("unroll")                                             \
            for (int j = 0; j < 8; j++) {                                 \
                float acc = 0.f;                                          \
                _Pragma("unroll")                                         \
                for (int k = 0; k < 11; k++)                              \
                    acc = fmaf(W11[k], v[j + k], acc);                    \
                OUT[j] = acc;                                             \
            }                                                             \
        }
        VCONV(m1,  o1)
        VCONV(m2,  o2)
        VCONV(mgg, ogg)
        VCONV(mrr, orr)
        VCONV(mgr, ogr)
#undef VCONV

#pragma unroll
        for (int j = 0; j < 8; j++) {
            float mu1 = o1[j], mu2 = o2[j];
            float mu1s = mu1 * mu1;
            float mu2s = mu2 * mu2;
            float mu12 = mu1 * mu2;
            float s11 = ogg[j] - mu1s;
            float s22 = orr[j] - mu2s;
            float s12 = ogr[j] - mu12;
            float num = (2.f * mu12 + C1F) * (2.f * s12 + C2F);
            float den = (mu1s + mu2s + C1F) * (s11 + s22 + C2F);
            lsum += __fdividef(num, den);
        }
    }

    // ---- Block reduction (fp32) ----
#pragma unroll
    for (int off = 16; off > 0; off >>= 1)
        lsum += __shfl_xor_sync(0xffffffffu, lsum, off);
    if ((tid & 31) == 0) wsum[tid >> 5] = lsum;
    __syncthreads();

    if (tid == 0) {
        float s = 0.f;
#pragma unroll
        for (int i = 0; i < 8; i++) s += wsum[i];
        int bid = blockIdx.x + NBX * (blockIdx.y + NBY * blockIdx.z);
        g_partials[bid] = s;
        __threadfence();
        unsigned int t = atomicAdd(&g_count, 1u);
        is_last = (t == (unsigned)(NBLK - 1));
    }
    __syncthreads();

    // ---- Last block: deterministic final reduction (fixed index order) ----
    if (is_last) {
        __threadfence();
        double acc = 0.0;
        for (int i = tid; i < NBLK; i += NT)
            acc += (double)g_partials[i];
#pragma unroll
        for (int off = 16; off > 0; off >>= 1)
            acc += __shfl_xor_sync(0xffffffffu, acc, off);
        if ((tid & 31) == 0) dsum[tid >> 5] = acc;
        __syncthreads();
        if (tid == 0) {
            double s = 0.0;
#pragma unroll
            for (int i = 0; i < 8; i++) s += dsum[i];
            out[0] = (float)(1.0 - s / NPIX);
            g_count = 0;   // self-reset -> graph-replay deterministic
        }
    }
}

extern "C" void kernel_launch(void* const* d_in, const int* in_sizes, int n_in,
                              void* d_out, int out_size) {
    const float* gen = (const float*)d_in[0];
    const float* ref = (const float*)d_in[1];
    float* out = (float*)d_out;

    dim3 grid(NBX, NBY, NPLANES);
    ssim_main<<<grid, NT>>>(gen, ref, out);
}